// round 1
// baseline (speedup 1.0000x reference)
#include <cuda_runtime.h>
#include <stdint.h>

#define BB 4
#define NN 2000
#define CC 80
#define NCLS 81
#define KPRE 2000
#define MAXOUT 100
#define CAP 8192
#define SCORE_THR 0.05f
#define IOU_THR 0.5f
#define MAX_RATIO 4.135166556742356f

// ------------------- scratch (device globals; no allocation) -------------------
__device__ int                g_cnt[BB];
__device__ unsigned long long g_keys[BB][CAP];
__device__ float              g_selscore[BB][KPRE];
__device__ int                g_selflat[BB][KPRE];
__device__ float4             g_box[BB][KPRE];    // clipped boxes (output)
__device__ float4             g_obox[BB][KPRE];   // class-offset boxes (for IoU, matches ref fp)
__device__ float              g_oarea[BB][KPRE];  // area from offset coords (matches ref fp)
__device__ int                g_label[BB][KPRE];
__device__ unsigned int       g_mask[BB][KPRE][64];  // suppression bitmask rows
__device__ int                g_outidx[BB][MAXOUT];

// ------------------- init -------------------
__global__ void k_init() {
    if (threadIdx.x < BB) g_cnt[threadIdx.x] = 0;
}

// ------------------- softmax + threshold + compact (warp per proposal) -------------------
__global__ void k_softmax(const float* __restrict__ cls) {
    int warp = (blockIdx.x * blockDim.x + threadIdx.x) >> 5;
    int lane = threadIdx.x & 31;
    if (warp >= BB * NN) return;
    int img = warp / NN, p = warp % NN;
    const float* row = cls + ((size_t)img * NN + p) * NCLS;

    float x0 = row[lane];
    float x1 = row[lane + 32];
    float x2 = (lane < NCLS - 64) ? row[lane + 64] : -1e30f;  // lanes 0..16 (c=64..80)
    float m = fmaxf(fmaxf(x0, x1), x2);
    #pragma unroll
    for (int o = 16; o; o >>= 1) m = fmaxf(m, __shfl_xor_sync(0xffffffffu, m, o));

    float e0 = expf(x0 - m);
    float e1 = expf(x1 - m);
    float e2 = (lane < NCLS - 64) ? expf(x2 - m) : 0.0f;
    float s = e0 + e1 + e2;
    #pragma unroll
    for (int o = 16; o; o >>= 1) s += __shfl_xor_sync(0xffffffffu, s, o);

    // emit candidates for foreground classes only (c < 80); background (c==80, lane 16 third slot) excluded
    #pragma unroll
    for (int grp = 0; grp < 3; grp++) {
        int c = lane + grp * 32;
        float e = (grp == 0) ? e0 : (grp == 1) ? e1 : e2;
        if (c < CC) {
            float sc = __fdiv_rn(e, s);
            if (sc > SCORE_THR) {
                int pos = atomicAdd(&g_cnt[img], 1);
                if (pos < CAP) {
                    unsigned flat = (unsigned)(p * CC + c);
                    g_keys[img][pos] =
                        ((unsigned long long)__float_as_uint(sc) << 32) |
                        (unsigned long long)(~flat);
                }
            }
        }
    }
}

// ------------------- per-image bitonic sort (descending), emit top-2000 -------------------
extern __shared__ unsigned long long s_keys[];
__global__ void k_sort() {
    int img = blockIdx.x;
    int cnt = min(g_cnt[img], CAP);
    int tid = threadIdx.x;  // 1024

    for (int e = tid; e < CAP; e += 1024)
        s_keys[e] = (e < cnt) ? g_keys[img][e] : 0ULL;
    __syncthreads();

    for (int k = 2; k <= CAP; k <<= 1) {
        for (int j = k >> 1; j > 0; j >>= 1) {
            for (int e = tid; e < CAP / 2; e += 1024) {
                int low = ((e & ~(j - 1)) << 1) | (e & (j - 1));
                int hi = low + j;
                bool desc = ((low & k) == 0);
                unsigned long long a = s_keys[low], b = s_keys[hi];
                bool sw = desc ? (a < b) : (a > b);
                if (sw) { s_keys[low] = b; s_keys[hi] = a; }
            }
            __syncthreads();
        }
    }

    for (int r = tid; r < KPRE; r += 1024) {
        unsigned long long key = s_keys[r];
        g_selscore[img][r] = __uint_as_float((unsigned)(key >> 32));
        g_selflat[img][r] = (int)(~(unsigned)key);
    }
}

// ------------------- decode selected boxes (match reference fp exactly: no FMA contraction) -------------------
__global__ void k_decode(const float* __restrict__ reg,
                         const float* __restrict__ props,
                         const int* __restrict__ hw) {
    int t = blockIdx.x * blockDim.x + threadIdx.x;
    if (t >= BB * KPRE) return;
    int img = t / KPRE, r = t % KPRE;
    float sc = g_selscore[img][r];
    if (sc > SCORE_THR) {
        int flat = g_selflat[img][r];
        int p = flat / CC, c = flat % CC;
        const float* pb = props + ((size_t)img * NN + p) * 4;
        const float* dd = reg + (((size_t)img * NN + p) * CC + c) * 4;
        float h = (float)hw[img * 2 + 0];
        float w = (float)hw[img * 2 + 1];

        float dx = __fmul_rn(dd[0], 0.1f);
        float dy = __fmul_rn(dd[1], 0.1f);
        float dw = fminf(fmaxf(__fmul_rn(dd[2], 0.2f), -MAX_RATIO), MAX_RATIO);
        float dh = fminf(fmaxf(__fmul_rn(dd[3], 0.2f), -MAX_RATIO), MAX_RATIO);

        float px = __fmul_rn(__fadd_rn(pb[0], pb[2]), 0.5f);
        float py = __fmul_rn(__fadd_rn(pb[1], pb[3]), 0.5f);
        float pw = __fsub_rn(pb[2], pb[0]);
        float ph = __fsub_rn(pb[3], pb[1]);

        float gx = __fadd_rn(px, __fmul_rn(pw, dx));
        float gy = __fadd_rn(py, __fmul_rn(ph, dy));
        float gw = __fmul_rn(pw, expf(dw));
        float gh = __fmul_rn(ph, expf(dh));
        float hx = __fmul_rn(gw, 0.5f);
        float hy = __fmul_rn(gh, 0.5f);

        float x1 = fminf(fmaxf(__fsub_rn(gx, hx), 0.0f), w);
        float y1 = fminf(fmaxf(__fsub_rn(gy, hy), 0.0f), h);
        float x2 = fminf(fmaxf(__fadd_rn(gx, hx), 0.0f), w);
        float y2 = fminf(fmaxf(__fadd_rn(gy, hy), 0.0f), h);

        g_box[img][r] = make_float4(x1, y1, x2, y2);
        // class-offset boxes exactly as the reference builds them (fp32 rounded)
        float off = __fmul_rn((float)c, __fadd_rn(fmaxf(h, w), 1.0f));
        float4 ob = make_float4(__fadd_rn(x1, off), __fadd_rn(y1, off),
                                __fadd_rn(x2, off), __fadd_rn(y2, off));
        g_obox[img][r] = ob;
        g_oarea[img][r] = __fmul_rn(__fsub_rn(ob.z, ob.x), __fsub_rn(ob.w, ob.y));
        g_label[img][r] = c;
    } else {
        g_box[img][r] = make_float4(0, 0, 0, 0);
        g_obox[img][r] = make_float4(0, 0, 0, 0);
        g_oarea[img][r] = 0.0f;
        g_label[img][r] = -1;
    }
}

// ------------------- suppression mask matrix -------------------
#define ROWS_PB 16
__global__ void k_mask() {
    __shared__ float4 sb[KPRE];
    __shared__ float sa[KPRE];
    int img = blockIdx.y;
    int tid = threadIdx.x;  // 256
    for (int e = tid; e < KPRE; e += 256) {
        sb[e] = g_obox[img][e];
        sa[e] = g_oarea[img][e];
    }
    __syncthreads();
    int warp = tid >> 5, lane = tid & 31;
    #pragma unroll
    for (int rr = 0; rr < 2; rr++) {
        int i = blockIdx.x * ROWS_PB + warp * 2 + rr;
        if (i >= KPRE) continue;
        float4 bi = sb[i];
        float ai = sa[i];
        for (int ch = 0; ch < 64; ch++) {
            int j = ch * 32 + lane;
            bool pred = false;
            if (j < KPRE && j > i) {
                float4 bj = sb[j];
                float ltx = fmaxf(bi.x, bj.x), lty = fmaxf(bi.y, bj.y);
                float rbx = fminf(bi.z, bj.z), rby = fminf(bi.w, bj.w);
                float wx = fmaxf(__fsub_rn(rbx, ltx), 0.0f);
                float wy = fmaxf(__fsub_rn(rby, lty), 0.0f);
                float inter = __fmul_rn(wx, wy);
                float denom = __fadd_rn(__fsub_rn(__fadd_rn(ai, sa[j]), inter), 1e-6f);
                pred = __fdiv_rn(inter, denom) > IOU_THR;
            }
            unsigned m = __ballot_sync(0xffffffffu, pred);
            if (lane == 0) g_mask[img][i][ch] = m;
        }
    }
}

// ------------------- sequential greedy reduce (warp per image, pipelined row fetch) -------------------
#define NCHK 16
__global__ void k_nms() {
    int warp = threadIdx.x >> 5;  // 0..3
    int lane = threadIdx.x & 31;
    int img = warp;

    // init remv from validity: invalid (score<=thr or i>=2000) starts suppressed
    unsigned r0 = 0, r1 = 0;
    for (int b = 0; b < 32; b++) {
        int i0 = lane * 32 + b;
        if (!(g_selscore[img][i0] > SCORE_THR)) r0 |= (1u << b);
        int i1 = (lane + 32) * 32 + b;
        if (i1 >= KPRE || !(g_selscore[img][i1] > SCORE_THR)) r1 |= (1u << b);
    }

    const unsigned* mbase = &g_mask[img][0][0];
    unsigned a0[NCHK], a1[NCHK], b0[NCHK], b1[NCHK];
    #pragma unroll
    for (int t = 0; t < NCHK; t++) {
        a0[t] = mbase[t * 64 + lane];
        a1[t] = mbase[t * 64 + lane + 32];
    }

    int outcnt = 0;
    for (int base = 0; base < KPRE; base += NCHK) {
        int nb = base + NCHK;
        #pragma unroll
        for (int t = 0; t < NCHK; t++) {
            int rrow = nb + t;
            if (rrow < KPRE) {
                b0[t] = mbase[rrow * 64 + lane];
                b1[t] = mbase[rrow * 64 + lane + 32];
            } else { b0[t] = 0; b1[t] = 0; }
        }
        #pragma unroll
        for (int t = 0; t < NCHK; t++) {
            int i = base + t;
            int w = i >> 5;
            unsigned word = __shfl_sync(0xffffffffu, (w < 32) ? r0 : r1, w & 31);
            if (!((word >> (i & 31)) & 1u)) {
                r0 |= a0[t];
                r1 |= a1[t];
                if (outcnt < MAXOUT) {
                    if (lane == 0) g_outidx[img][outcnt] = i;
                    outcnt++;
                }
            }
        }
        #pragma unroll
        for (int t = 0; t < NCHK; t++) { a0[t] = b0[t]; a1[t] = b1[t]; }
    }
    if (lane == 0)
        for (int k = outcnt; k < MAXOUT; k++) g_outidx[img][k] = -1;
}

// ------------------- emit output: boxes[B,100,4] | scores[B,100] | labels[B,100] -------------------
__global__ void k_out(float* __restrict__ out) {
    int t = blockIdx.x * blockDim.x + threadIdx.x;
    if (t >= BB * MAXOUT) return;
    int img = t / MAXOUT, k = t % MAXOUT;
    int idx = g_outidx[img][k];
    float4 bx = make_float4(0, 0, 0, 0);
    float sc = 0.0f, lb = -1.0f;
    if (idx >= 0) {
        bx = g_box[img][idx];
        sc = g_selscore[img][idx];
        lb = (float)g_label[img][idx];
    }
    float* bo = out + (size_t)(img * MAXOUT + k) * 4;
    bo[0] = bx.x; bo[1] = bx.y; bo[2] = bx.z; bo[3] = bx.w;
    out[BB * MAXOUT * 4 + img * MAXOUT + k] = sc;
    out[BB * MAXOUT * 5 + img * MAXOUT + k] = lb;
}

// ------------------- launch -------------------
extern "C" void kernel_launch(void* const* d_in, const int* in_sizes, int n_in,
                              void* d_out, int out_size) {
    const float* cls = (const float*)d_in[0];
    const float* reg = (const float*)d_in[1];
    const float* props = (const float*)d_in[2];
    const int* hw = (const int*)d_in[3];
    float* out = (float*)d_out;

    cudaFuncSetAttribute(k_sort, cudaFuncAttributeMaxDynamicSharedMemorySize, CAP * 8);

    k_init<<<1, 32>>>();
    k_softmax<<<(BB * NN * 32 + 255) / 256, 256>>>(cls);
    k_sort<<<BB, 1024, CAP * 8>>>();
    k_decode<<<(BB * KPRE + 255) / 256, 256>>>(reg, props, hw);
    dim3 mg(KPRE / ROWS_PB, BB);
    k_mask<<<mg, 256>>>();
    k_nms<<<1, 128>>>();
    k_out<<<(BB * MAXOUT + 127) / 128, 128>>>(out);
}

// round 2
// speedup vs baseline: 1.2628x; 1.2628x over previous
#include <cuda_runtime.h>
#include <stdint.h>

#define BB 4
#define NN 2000
#define CC 80
#define NCLS 81
#define KPRE 2000
#define MAXOUT 100
#define CAP 8192
#define CAP2 4096
#define NHIST 1024
#define SCORE_THR 0.05f
#define IOU_THR 0.5f
#define MAX_RATIO 4.135166556742356f

// ------------------- scratch (device globals; no allocation) -------------------
__device__ int                g_cnt[BB];
__device__ int                g_hist[BB][NHIST];
__device__ int                g_bcut[BB];
__device__ unsigned long long g_keys[BB][CAP];
__device__ float              g_selscore[BB][KPRE];
__device__ int                g_selflat[BB][KPRE];
__device__ float4             g_box[BB][KPRE];
__device__ float4             g_obox[BB][KPRE];
__device__ float              g_oarea[BB][KPRE];
__device__ int                g_label[BB][KPRE];
__device__ unsigned int       g_mask[BB][KPRE][64];
__device__ int                g_outidx[BB][MAXOUT];

__device__ __forceinline__ int bucket_of(unsigned bits) {
    int b = (int)(bits >> 16) - 0x3D00;
    return min(NHIST - 1, max(0, b));
}

// ------------------- init: zero counters + histograms -------------------
__global__ void k_init() {
    int t = blockIdx.x * blockDim.x + threadIdx.x;
    if (t < BB * NHIST) ((int*)g_hist)[t] = 0;
    if (t < BB) g_cnt[t] = 0;
}

// ------------------- softmax + threshold + compact + histogram -------------------
__global__ void k_softmax(const float* __restrict__ cls) {
    int warp = (blockIdx.x * blockDim.x + threadIdx.x) >> 5;
    int lane = threadIdx.x & 31;
    if (warp >= BB * NN) return;
    int img = warp / NN, p = warp % NN;
    const float* row = cls + ((size_t)img * NN + p) * NCLS;

    float x0 = row[lane];
    float x1 = row[lane + 32];
    float x2 = (lane < NCLS - 64) ? row[lane + 64] : -1e30f;
    float m = fmaxf(fmaxf(x0, x1), x2);
    #pragma unroll
    for (int o = 16; o; o >>= 1) m = fmaxf(m, __shfl_xor_sync(0xffffffffu, m, o));

    float e0 = expf(x0 - m);
    float e1 = expf(x1 - m);
    float e2 = (lane < NCLS - 64) ? expf(x2 - m) : 0.0f;
    float s = e0 + e1 + e2;
    #pragma unroll
    for (int o = 16; o; o >>= 1) s += __shfl_xor_sync(0xffffffffu, s, o);

    #pragma unroll
    for (int grp = 0; grp < 3; grp++) {
        int c = lane + grp * 32;
        float e = (grp == 0) ? e0 : (grp == 1) ? e1 : e2;
        if (c < CC) {
            float sc = __fdiv_rn(e, s);
            if (sc > SCORE_THR) {
                int pos = atomicAdd(&g_cnt[img], 1);
                if (pos < CAP) {
                    unsigned flat = (unsigned)(p * CC + c);
                    unsigned sb = __float_as_uint(sc);
                    g_keys[img][pos] =
                        ((unsigned long long)sb << 32) | (unsigned long long)(~flat);
                    atomicAdd(&g_hist[img][bucket_of(sb)], 1);
                }
            }
        }
    }
}

// ------------------- cutoff bucket: largest b with suffix(b) >= min(2000, total) -------------------
__global__ void k_cutoff() {
    __shared__ int sh[NHIST];
    __shared__ int s_bcut;
    int img = blockIdx.x, tid = threadIdx.x;  // 1024
    sh[tid] = g_hist[img][tid];
    if (tid == 0) s_bcut = NHIST;  // default: keep none (total==0)
    for (int off = 1; off < NHIST; off <<= 1) {
        __syncthreads();
        int v = (tid + off < NHIST) ? sh[tid + off] : 0;
        __syncthreads();
        sh[tid] += v;
    }
    __syncthreads();
    int total = sh[0];
    int target = min(KPRE, total);
    if (total > 0) {
        if (sh[tid] >= target && (tid == NHIST - 1 || sh[tid + 1] < target))
            atomicMax(&s_bcut, 0), s_bcut = tid;  // unique thread
    }
    __syncthreads();
    if (tid == 0) g_bcut[img] = s_bcut;
}

// ------------------- filter-by-bucket + bitonic sort 4096 (descending), emit top-2000 -------------------
__global__ void k_sort() {
    __shared__ unsigned long long sk[CAP2];
    __shared__ int scnt;
    int img = blockIdx.x, tid = threadIdx.x;  // 1024
    int cnt = min(g_cnt[img], CAP);
    int bcut = g_bcut[img];
    if (tid == 0) scnt = 0;
    for (int e = tid; e < CAP2; e += 1024) sk[e] = 0ULL;
    __syncthreads();
    for (int e = tid; e < cnt; e += 1024) {
        unsigned long long key = g_keys[img][e];
        if (bucket_of((unsigned)(key >> 32)) >= bcut) {
            int pos = atomicAdd(&scnt, 1);
            if (pos < CAP2) sk[pos] = key;
        }
    }
    __syncthreads();
    for (int k = 2; k <= CAP2; k <<= 1) {
        for (int j = k >> 1; j > 0; j >>= 1) {
            for (int e = tid; e < CAP2 / 2; e += 1024) {
                int lo = ((e & ~(j - 1)) << 1) | (e & (j - 1));
                int hi = lo + j;
                bool desc = ((lo & k) == 0);
                unsigned long long a = sk[lo], b = sk[hi];
                if (desc ? (a < b) : (a > b)) { sk[lo] = b; sk[hi] = a; }
            }
            __syncthreads();
        }
    }
    for (int r = tid; r < KPRE; r += 1024) {
        unsigned long long key = sk[r];
        g_selscore[img][r] = __uint_as_float((unsigned)(key >> 32));
        g_selflat[img][r] = (int)(~(unsigned)key);
    }
}

// ------------------- decode selected boxes (no FMA contraction; matches ref fp) -------------------
__global__ void k_decode(const float* __restrict__ reg,
                         const float* __restrict__ props,
                         const int* __restrict__ hw) {
    int t = blockIdx.x * blockDim.x + threadIdx.x;
    if (t >= BB * KPRE) return;
    int img = t / KPRE, r = t % KPRE;
    float sc = g_selscore[img][r];
    if (sc > SCORE_THR) {
        int flat = g_selflat[img][r];
        int p = flat / CC, c = flat % CC;
        const float* pb = props + ((size_t)img * NN + p) * 4;
        const float* dd = reg + (((size_t)img * NN + p) * CC + c) * 4;
        float h = (float)hw[img * 2 + 0];
        float w = (float)hw[img * 2 + 1];

        float dx = __fmul_rn(dd[0], 0.1f);
        float dy = __fmul_rn(dd[1], 0.1f);
        float dw = fminf(fmaxf(__fmul_rn(dd[2], 0.2f), -MAX_RATIO), MAX_RATIO);
        float dh = fminf(fmaxf(__fmul_rn(dd[3], 0.2f), -MAX_RATIO), MAX_RATIO);

        float px = __fmul_rn(__fadd_rn(pb[0], pb[2]), 0.5f);
        float py = __fmul_rn(__fadd_rn(pb[1], pb[3]), 0.5f);
        float pw = __fsub_rn(pb[2], pb[0]);
        float ph = __fsub_rn(pb[3], pb[1]);

        float gx = __fadd_rn(px, __fmul_rn(pw, dx));
        float gy = __fadd_rn(py, __fmul_rn(ph, dy));
        float gw = __fmul_rn(pw, expf(dw));
        float gh = __fmul_rn(ph, expf(dh));
        float hx = __fmul_rn(gw, 0.5f);
        float hy = __fmul_rn(gh, 0.5f);

        float x1 = fminf(fmaxf(__fsub_rn(gx, hx), 0.0f), w);
        float y1 = fminf(fmaxf(__fsub_rn(gy, hy), 0.0f), h);
        float x2 = fminf(fmaxf(__fadd_rn(gx, hx), 0.0f), w);
        float y2 = fminf(fmaxf(__fadd_rn(gy, hy), 0.0f), h);

        g_box[img][r] = make_float4(x1, y1, x2, y2);
        float off = __fmul_rn((float)c, __fadd_rn(fmaxf(h, w), 1.0f));
        float4 ob = make_float4(__fadd_rn(x1, off), __fadd_rn(y1, off),
                                __fadd_rn(x2, off), __fadd_rn(y2, off));
        g_obox[img][r] = ob;
        g_oarea[img][r] = __fmul_rn(__fsub_rn(ob.z, ob.x), __fsub_rn(ob.w, ob.y));
        g_label[img][r] = c;
    } else {
        g_box[img][r] = make_float4(0, 0, 0, 0);
        g_obox[img][r] = make_float4(0, 0, 0, 0);
        g_oarea[img][r] = 0.0f;
        g_label[img][r] = -1;
    }
}

// ------------------- suppression mask matrix (upper triangle only) -------------------
#define ROWS_PB 32
__global__ void k_mask() {
    __shared__ float4 sb[KPRE];
    __shared__ float sa[KPRE];
    int img = blockIdx.y;
    int tid = threadIdx.x;  // 256
    for (int e = tid; e < KPRE; e += 256) {
        sb[e] = g_obox[img][e];
        sa[e] = g_oarea[img][e];
    }
    __syncthreads();
    int warp = tid >> 5, lane = tid & 31;
    #pragma unroll
    for (int rr = 0; rr < 4; rr++) {
        int i = blockIdx.x * ROWS_PB + warp * 4 + rr;
        if (i >= KPRE) continue;
        float4 bi = sb[i];
        float ai = sa[i];
        int w0 = i >> 5;
        for (int z = lane; z < w0; z += 32) g_mask[img][i][z] = 0u;
        for (int ch = w0; ch < 64; ch++) {
            int j = ch * 32 + lane;
            bool pred = false;
            if (j < KPRE && j > i) {
                float4 bj = sb[j];
                float ltx = fmaxf(bi.x, bj.x), lty = fmaxf(bi.y, bj.y);
                float rbx = fminf(bi.z, bj.z), rby = fminf(bi.w, bj.w);
                float wx = fmaxf(__fsub_rn(rbx, ltx), 0.0f);
                float wy = fmaxf(__fsub_rn(rby, lty), 0.0f);
                float inter = __fmul_rn(wx, wy);
                float denom = __fadd_rn(__fsub_rn(__fadd_rn(ai, sa[j]), inter), 1e-6f);
                pred = __fdiv_rn(inter, denom) > IOU_THR;
            }
            unsigned m = __ballot_sync(0xffffffffu, pred);
            if (lane == 0) g_mask[img][i][ch] = m;
        }
    }
}

// ------------------- greedy NMS, block-32 resolution + output emit (warp per image) -------------------
#define NB ((KPRE + 31) / 32)
__global__ void k_nms_out(float* __restrict__ out) {
    int warp = threadIdx.x >> 5;  // 0..3
    int lane = threadIdx.x & 31;
    int img = warp;

    // remv init: bit set = suppressed; invalid rows start suppressed
    unsigned r0 = 0, r1 = 0;
    #pragma unroll 4
    for (int b = 0; b < 32; b++) {
        int i0 = lane * 32 + b;
        if (!(g_selscore[img][i0] > SCORE_THR)) r0 |= (1u << b);
        int i1 = (lane + 32) * 32 + b;
        if (i1 >= KPRE || !(g_selscore[img][i1] > SCORE_THR)) r1 |= (1u << b);
    }

    const unsigned* mb = &g_mask[img][0][0];
    unsigned a0[32], a1[32], n0[32], n1[32];
    unsigned diag, ndiag;
    #pragma unroll
    for (int t = 0; t < 32; t++) {
        a0[t] = mb[t * 64 + lane];
        a1[t] = mb[t * 64 + lane + 32];
    }
    diag = (lane < KPRE) ? mb[lane * 64 + 0] : 0u;

    int outcnt = 0;
    for (int b = 0; b < NB; b++) {
        int nb = b + 1;
        if (nb < NB) {
            int base = nb * 32;
            #pragma unroll
            for (int t = 0; t < 32; t++) {
                int row = base + t;
                n0[t] = (row < KPRE) ? mb[row * 64 + lane] : 0u;
                n1[t] = (row < KPRE) ? mb[row * 64 + lane + 32] : 0u;
            }
            int drow = base + lane;
            ndiag = (drow < KPRE) ? mb[drow * 64 + nb] : 0u;
        } else { ndiag = 0u; }

        unsigned cur = (b < 32) ? __shfl_sync(0xffffffffu, r0, b)
                                : __shfl_sync(0xffffffffu, r1, b - 32);
        unsigned alive = cur, kept = 0;
        #pragma unroll
        for (int t = 0; t < 32; t++) {
            unsigned dgt = __shfl_sync(0xffffffffu, diag, t);  // independent of alive: hoistable
            if (!((alive >> t) & 1u)) { kept |= (1u << t); alive |= dgt; }
        }
        #pragma unroll
        for (int t = 0; t < 32; t++) {
            if ((kept >> t) & 1u) { r0 |= a0[t]; r1 |= a1[t]; }
        }
        int base = b * 32;
        unsigned km = kept;
        while (km && outcnt < MAXOUT) {
            int t = __ffs(km) - 1; km &= km - 1;
            if (lane == 0) g_outidx[img][outcnt] = base + t;
            outcnt++;
        }
        #pragma unroll
        for (int t = 0; t < 32; t++) { a0[t] = n0[t]; a1[t] = n1[t]; }
        diag = ndiag;
    }
    if (lane == 0)
        for (int k = outcnt; k < MAXOUT; k++) g_outidx[img][k] = -1;
    __syncwarp();

    // emit: boxes[B,100,4] | scores[B,100] | labels[B,100]
    for (int k = lane; k < MAXOUT; k += 32) {
        int idx = g_outidx[img][k];
        float4 bx = make_float4(0, 0, 0, 0);
        float sc = 0.0f, lb = -1.0f;
        if (idx >= 0) {
            bx = g_box[img][idx];
            sc = g_selscore[img][idx];
            lb = (float)g_label[img][idx];
        }
        float* bo = out + (size_t)(img * MAXOUT + k) * 4;
        bo[0] = bx.x; bo[1] = bx.y; bo[2] = bx.z; bo[3] = bx.w;
        out[BB * MAXOUT * 4 + img * MAXOUT + k] = sc;
        out[BB * MAXOUT * 5 + img * MAXOUT + k] = lb;
    }
}

// ------------------- launch -------------------
extern "C" void kernel_launch(void* const* d_in, const int* in_sizes, int n_in,
                              void* d_out, int out_size) {
    const float* cls = (const float*)d_in[0];
    const float* reg = (const float*)d_in[1];
    const float* props = (const float*)d_in[2];
    const int* hw = (const int*)d_in[3];
    float* out = (float*)d_out;

    k_init<<<(BB * NHIST + 255) / 256, 256>>>();
    k_softmax<<<(BB * NN * 32 + 255) / 256, 256>>>(cls);
    k_cutoff<<<BB, NHIST>>>();
    k_sort<<<BB, 1024>>>();
    k_decode<<<(BB * KPRE + 255) / 256, 256>>>(reg, props, hw);
    dim3 mg((KPRE + ROWS_PB - 1) / ROWS_PB, BB);
    k_mask<<<mg, 256>>>();
    k_nms_out<<<1, 128>>>(out);
}

// round 3
// speedup vs baseline: 2.1959x; 1.7389x over previous
#include <cuda_runtime.h>
#include <stdint.h>

#define BB 4
#define NN 2000
#define CC 80
#define NCLS 81
#define KPRE 2000
#define MAXOUT 100
#define CAP 8192
#define SCAP 4096
#define NHIST 5120
#define HBASE 0x1EA66
#define SCORE_THR 0.05f
#define IOU_THR 0.5f
#define MAX_RATIO 4.135166556742356f
#define NB ((KPRE + 31) / 32)   /* 63 */

// ------------------- scratch (device globals; no allocation) -------------------
__device__ int                g_cnt[BB];
__device__ int                g_hist[BB][NHIST];
__device__ int                g_bcnt[BB][NHIST];
__device__ int                g_off[BB][NHIST];
__device__ unsigned long long g_keys[BB][CAP];
__device__ unsigned long long g_skeys[BB][SCAP];
__device__ float4             g_box[BB][KPRE];
__device__ float4             g_obox[BB][KPRE];
__device__ float              g_oarea[BB][KPRE];
__device__ int                g_label[BB][KPRE];
__device__ unsigned int       g_mask[BB][KPRE][64];
__device__ int                g_outidx[BB][MAXOUT];

__device__ __forceinline__ int bucket_of(unsigned bits) {
    int b = (int)(bits >> 13) - HBASE;
    return min(NHIST - 1, max(0, b));
}

// ------------------- init -------------------
__global__ void k_init() {
    int t = blockIdx.x * blockDim.x + threadIdx.x;
    if (t < BB * NHIST) { ((int*)g_hist)[t] = 0; ((int*)g_bcnt)[t] = 0; }
    if (t < BB * SCAP) ((unsigned long long*)g_skeys)[t] = 0ULL;
    if (t < BB) g_cnt[t] = 0;
}

// ------------------- softmax + threshold + compact + histogram -------------------
__global__ void k_softmax(const float* __restrict__ cls) {
    int warp = (blockIdx.x * blockDim.x + threadIdx.x) >> 5;
    int lane = threadIdx.x & 31;
    if (warp >= BB * NN) return;
    int img = warp / NN, p = warp % NN;
    const float* row = cls + ((size_t)img * NN + p) * NCLS;

    float x0 = row[lane];
    float x1 = row[lane + 32];
    float x2 = (lane < NCLS - 64) ? row[lane + 64] : -1e30f;
    float m = fmaxf(fmaxf(x0, x1), x2);
    #pragma unroll
    for (int o = 16; o; o >>= 1) m = fmaxf(m, __shfl_xor_sync(0xffffffffu, m, o));

    float e0 = expf(x0 - m);
    float e1 = expf(x1 - m);
    float e2 = (lane < NCLS - 64) ? expf(x2 - m) : 0.0f;
    float s = e0 + e1 + e2;
    #pragma unroll
    for (int o = 16; o; o >>= 1) s += __shfl_xor_sync(0xffffffffu, s, o);

    #pragma unroll
    for (int grp = 0; grp < 3; grp++) {
        int c = lane + grp * 32;
        float e = (grp == 0) ? e0 : (grp == 1) ? e1 : e2;
        if (c < CC) {
            float sc = __fdiv_rn(e, s);
            if (sc > SCORE_THR) {
                int pos = atomicAdd(&g_cnt[img], 1);
                if (pos < CAP) {
                    unsigned flat = (unsigned)(p * CC + c);
                    unsigned sb = __float_as_uint(sc);
                    g_keys[img][pos] =
                        ((unsigned long long)sb << 32) | (unsigned long long)(~flat);
                    atomicAdd(&g_hist[img][bucket_of(sb)], 1);
                }
            }
        }
    }
}

// ------------------- per-image suffix scan: off[b] = #keys in buckets > b -------------------
#define SCAN_U (NHIST / 1024)   /* 5 */
__global__ void k_scan() {
    __shared__ int s_wtot[32];
    int img = blockIdx.x, t = threadIdx.x;  // 1024
    int lane = t & 31, wid = t >> 5;

    int cnt[SCAN_U];
    int tsum = 0;
    #pragma unroll
    for (int u = 0; u < SCAN_U; u++) {
        int rb = t * SCAN_U + u;          // descending rank
        int b = NHIST - 1 - rb;
        cnt[u] = g_hist[img][b];
        tsum += cnt[u];
    }
    // warp inclusive scan of tsum
    int ws = tsum;
    #pragma unroll
    for (int o = 1; o < 32; o <<= 1) {
        int v = __shfl_up_sync(0xffffffffu, ws, o);
        if (lane >= o) ws += v;
    }
    if (lane == 31) s_wtot[wid] = ws;
    __syncthreads();
    if (wid == 0) {
        int v = s_wtot[lane];
        int sv = v;
        #pragma unroll
        for (int o = 1; o < 32; o <<= 1) {
            int x = __shfl_up_sync(0xffffffffu, sv, o);
            if (lane >= o) sv += x;
        }
        s_wtot[lane] = sv - v;  // exclusive warp base
    }
    __syncthreads();
    int base = s_wtot[wid] + (ws - tsum);  // exclusive offset for this thread
    #pragma unroll
    for (int u = 0; u < SCAN_U; u++) {
        int rb = t * SCAN_U + u;
        int b = NHIST - 1 - rb;
        g_off[img][b] = base;
        base += cnt[u];
    }
}

// ------------------- scatter keys to final (bucket-ordered) positions -------------------
__global__ void k_scatter() {
    int img = blockIdx.y;
    int e = blockIdx.x * blockDim.x + threadIdx.x;
    int cnt = min(g_cnt[img], CAP);
    if (e >= cnt) return;
    unsigned long long key = g_keys[img][e];
    int b = bucket_of((unsigned)(key >> 32));
    int o = g_off[img][b];
    if (o < 2048) {
        int pos = o + atomicAdd(&g_bcnt[img][b], 1);
        if (pos < SCAP) g_skeys[img][pos] = key;
    }
}

// ------------------- per-bucket tiny insertion sort (descending by full key) -------------------
__global__ void k_segsort() {
    int t = blockIdx.x * blockDim.x + threadIdx.x;
    if (t >= BB * NHIST) return;
    int img = t / NHIST, b = t % NHIST;
    int o = g_off[img][b];
    if (o >= 2048) return;
    int n = g_bcnt[img][b];
    int end = min(o + n, SCAP);
    unsigned long long* a = &g_skeys[img][0];
    for (int i = o + 1; i < end; i++) {
        unsigned long long v = a[i];
        int j = i - 1;
        while (j >= o && a[j] < v) { a[j + 1] = a[j]; j--; }
        a[j + 1] = v;
    }
}

// ------------------- decode selected boxes (no FMA contraction; matches ref fp) -------------------
__global__ void k_decode(const float* __restrict__ reg,
                         const float* __restrict__ props,
                         const int* __restrict__ hw) {
    int t = blockIdx.x * blockDim.x + threadIdx.x;
    if (t >= BB * KPRE) return;
    int img = t / KPRE, r = t % KPRE;
    unsigned long long key = g_skeys[img][r];
    float sc = __uint_as_float((unsigned)(key >> 32));
    if (sc > SCORE_THR) {
        int flat = (int)(~(unsigned)key);
        int p = flat / CC, c = flat % CC;
        const float* pb = props + ((size_t)img * NN + p) * 4;
        const float* dd = reg + (((size_t)img * NN + p) * CC + c) * 4;
        float h = (float)hw[img * 2 + 0];
        float w = (float)hw[img * 2 + 1];

        float dx = __fmul_rn(dd[0], 0.1f);
        float dy = __fmul_rn(dd[1], 0.1f);
        float dw = fminf(fmaxf(__fmul_rn(dd[2], 0.2f), -MAX_RATIO), MAX_RATIO);
        float dh = fminf(fmaxf(__fmul_rn(dd[3], 0.2f), -MAX_RATIO), MAX_RATIO);

        float px = __fmul_rn(__fadd_rn(pb[0], pb[2]), 0.5f);
        float py = __fmul_rn(__fadd_rn(pb[1], pb[3]), 0.5f);
        float pw = __fsub_rn(pb[2], pb[0]);
        float ph = __fsub_rn(pb[3], pb[1]);

        float gx = __fadd_rn(px, __fmul_rn(pw, dx));
        float gy = __fadd_rn(py, __fmul_rn(ph, dy));
        float gw = __fmul_rn(pw, expf(dw));
        float gh = __fmul_rn(ph, expf(dh));
        float hx = __fmul_rn(gw, 0.5f);
        float hy = __fmul_rn(gh, 0.5f);

        float x1 = fminf(fmaxf(__fsub_rn(gx, hx), 0.0f), w);
        float y1 = fminf(fmaxf(__fsub_rn(gy, hy), 0.0f), h);
        float x2 = fminf(fmaxf(__fadd_rn(gx, hx), 0.0f), w);
        float y2 = fminf(fmaxf(__fadd_rn(gy, hy), 0.0f), h);

        g_box[img][r] = make_float4(x1, y1, x2, y2);
        float off = __fmul_rn((float)c, __fadd_rn(fmaxf(h, w), 1.0f));
        float4 ob = make_float4(__fadd_rn(x1, off), __fadd_rn(y1, off),
                                __fadd_rn(x2, off), __fadd_rn(y2, off));
        g_obox[img][r] = ob;
        g_oarea[img][r] = __fmul_rn(__fsub_rn(ob.z, ob.x), __fsub_rn(ob.w, ob.y));
        g_label[img][r] = c;
    } else {
        g_box[img][r] = make_float4(0, 0, 0, 0);
        g_obox[img][r] = make_float4(0, 0, 0, 0);
        g_oarea[img][r] = 0.0f;
        g_label[img][r] = -1;
    }
}

// ------------------- suppression mask matrix (upper triangle only) -------------------
#define ROWS_PB 32
__global__ void k_mask() {
    __shared__ float4 sb[KPRE];
    __shared__ float sa[KPRE];
    int img = blockIdx.y;
    int tid = threadIdx.x;  // 256
    for (int e = tid; e < KPRE; e += 256) {
        sb[e] = g_obox[img][e];
        sa[e] = g_oarea[img][e];
    }
    __syncthreads();
    int warp = tid >> 5, lane = tid & 31;
    #pragma unroll
    for (int rr = 0; rr < 4; rr++) {
        int i = blockIdx.x * ROWS_PB + warp * 4 + rr;
        if (i >= KPRE) continue;
        float4 bi = sb[i];
        float ai = sa[i];
        int w0 = i >> 5;
        for (int z = lane; z < w0; z += 32) g_mask[img][i][z] = 0u;
        for (int ch = w0; ch < 64; ch++) {
            int j = ch * 32 + lane;
            bool pred = false;
            if (j < KPRE && j > i) {
                float4 bj = sb[j];
                float ltx = fmaxf(bi.x, bj.x), lty = fmaxf(bi.y, bj.y);
                float rbx = fminf(bi.z, bj.z), rby = fminf(bi.w, bj.w);
                float wx = fmaxf(__fsub_rn(rbx, ltx), 0.0f);
                float wy = fmaxf(__fsub_rn(rby, lty), 0.0f);
                float inter = __fmul_rn(wx, wy);
                float denom = __fadd_rn(__fsub_rn(__fadd_rn(ai, sa[j]), inter), 1e-6f);
                pred = __fdiv_rn(inter, denom) > IOU_THR;
            }
            unsigned m = __ballot_sync(0xffffffffu, pred);
            if (lane == 0) g_mask[img][i][ch] = m;
        }
    }
}

// ------------------- greedy NMS with early stop at 100 kept + output emit -------------------
__global__ void k_nms_out(float* __restrict__ out) {
    int img = blockIdx.x;
    int lane = threadIdx.x;  // 32 threads
    __shared__ unsigned sdg[32];

    const unsigned long long* keys = g_skeys[img];
    unsigned r0 = 0, r1 = 0;   // bit set = suppressed
    #pragma unroll 4
    for (int b = 0; b < 32; b++) {
        int i0 = lane * 32 + b;
        float s0 = __uint_as_float((unsigned)(keys[i0] >> 32));
        if (!(s0 > SCORE_THR)) r0 |= (1u << b);
        int i1 = (lane + 32) * 32 + b;
        float s1 = (i1 < KPRE) ? __uint_as_float((unsigned)(keys[i1] >> 32)) : 0.0f;
        if (!(s1 > SCORE_THR)) r1 |= (1u << b);
    }

    const unsigned* mb = &g_mask[img][0][0];
    int outcnt = 0;
    for (int b = 0; b < NB && outcnt < MAXOUT; b++) {
        int base = b * 32;
        // batched loads: full rows of this block + diagonal column word
        unsigned a0[32], a1[32];
        #pragma unroll
        for (int t = 0; t < 32; t++) {
            int row = base + t;
            a0[t] = (row < KPRE) ? mb[row * 64 + lane] : 0u;
            a1[t] = (row < KPRE) ? mb[row * 64 + lane + 32] : 0u;
        }
        int drow = base + lane;
        sdg[lane] = (drow < KPRE) ? mb[drow * 64 + b] : 0u;
        __syncwarp();

        unsigned cur = (b < 32) ? __shfl_sync(0xffffffffu, r0, b)
                                : __shfl_sync(0xffffffffu, r1, b - 32);
        unsigned rem = ~cur;
        unsigned kept = 0;
        while (rem) {
            int t = __ffs(rem) - 1;
            kept |= (1u << t);
            rem &= ~(sdg[t] | (1u << t));
        }
        #pragma unroll
        for (int t = 0; t < 32; t++)
            if ((kept >> t) & 1u) { r0 |= a0[t]; r1 |= a1[t]; }

        unsigned km = kept;
        while (km && outcnt < MAXOUT) {
            int t = __ffs(km) - 1; km &= km - 1;
            if (lane == 0) g_outidx[img][outcnt] = base + t;
            outcnt++;
        }
        __syncwarp();
    }
    if (lane == 0)
        for (int k = outcnt; k < MAXOUT; k++) g_outidx[img][k] = -1;
    __syncwarp();

    // emit: boxes[B,100,4] | scores[B,100] | labels[B,100]
    for (int k = lane; k < MAXOUT; k += 32) {
        int idx = g_outidx[img][k];
        float4 bx = make_float4(0, 0, 0, 0);
        float sc = 0.0f, lb = -1.0f;
        if (idx >= 0) {
            bx = g_box[img][idx];
            sc = __uint_as_float((unsigned)(keys[idx] >> 32));
            lb = (float)g_label[img][idx];
        }
        float* bo = out + (size_t)(img * MAXOUT + k) * 4;
        bo[0] = bx.x; bo[1] = bx.y; bo[2] = bx.z; bo[3] = bx.w;
        out[BB * MAXOUT * 4 + img * MAXOUT + k] = sc;
        out[BB * MAXOUT * 5 + img * MAXOUT + k] = lb;
    }
}

// ------------------- launch -------------------
extern "C" void kernel_launch(void* const* d_in, const int* in_sizes, int n_in,
                              void* d_out, int out_size) {
    const float* cls = (const float*)d_in[0];
    const float* reg = (const float*)d_in[1];
    const float* props = (const float*)d_in[2];
    const int* hw = (const int*)d_in[3];
    float* out = (float*)d_out;

    k_init<<<(BB * NHIST + 255) / 256, 256>>>();
    k_softmax<<<(BB * NN * 32 + 255) / 256, 256>>>(cls);
    k_scan<<<BB, 1024>>>();
    dim3 sg(CAP / 1024, BB);
    k_scatter<<<sg, 1024>>>();
    k_segsort<<<(BB * NHIST + 255) / 256, 256>>>();
    k_decode<<<(BB * KPRE + 255) / 256, 256>>>(reg, props, hw);
    dim3 mg((KPRE + ROWS_PB - 1) / ROWS_PB, BB);
    k_mask<<<mg, 256>>>();
    k_nms_out<<<BB, 32>>>(out);
}